// round 1
// baseline (speedup 1.0000x reference)
#include <cuda_runtime.h>

// LSTM (H=64, in=1, T=1024, B=4096) + Linear(64->30), fp32.
// One block per SM. Thread t owns gate-row t of W_hh in registers (as f32x2
// pairs); h lives in smem (broadcast LDS.128); packed fma.rn.f32x2 matvec.
// Fixed (hidden j, batch b) -> thread task map keeps c in registers.

#define HID      64
#define NG       256      // 4*HID
#define SEQ_T    1024
#define NBATCH   4096
#define NFC      30
#define NB       28       // batch sequences per block
#define NTHREADS 256
#define XCHUNK   32       // x prefetch chunk (steps)
#define NTASK    7        // NB*HID / NTHREADS = 1792/256

__device__ __forceinline__ float fast_ex2(float x) {
    float r; asm("ex2.approx.f32 %0, %1;" : "=f"(r) : "f"(x)); return r;
}
__device__ __forceinline__ float fast_rcp(float x) {
    float r; asm("rcp.approx.f32 %0, %1;" : "=f"(r) : "f"(x)); return r;
}
// sigmoid(x) = 1/(1+2^(-x*log2 e))   (accurate to ~few ulp; saturates correctly)
__device__ __forceinline__ float sigm(float x) {
    return fast_rcp(1.0f + fast_ex2(-1.4426950408889634f * x));
}
// tanh(x) = 1 - 2/(1+2^(2x*log2 e))  (handles +/-inf via rcp(inf)=0)
__device__ __forceinline__ float tanh_fast(float x) {
    return 1.0f - 2.0f * fast_rcp(1.0f + fast_ex2(2.8853900817779268f * x));
}

__device__ __forceinline__ unsigned long long pack2(float lo, float hi) {
    unsigned long long r;
    asm("mov.b64 %0, {%1, %2};" : "=l"(r) : "f"(lo), "f"(hi));
    return r;
}
__device__ __forceinline__ void unpack2(unsigned long long v, float& lo, float& hi) {
    asm("mov.b64 {%0, %1}, %2;" : "=f"(lo), "=f"(hi) : "l"(v));
}
// Packed dual fp32 FMA (Blackwell): d = a*b + d on both lanes.
__device__ __forceinline__ void ffma2(unsigned long long& d,
                                      unsigned long long a,
                                      unsigned long long b) {
    asm("fma.rn.f32x2 %0, %1, %2, %0;" : "+l"(d) : "l"(a), "l"(b));
}

__global__ void __launch_bounds__(NTHREADS, 1)
lstm_fused(const float* __restrict__ x,      // [B, T]
           const float* __restrict__ W_ih,   // [256] (input dim 1)
           const float* __restrict__ W_hh,   // [256, 64]
           const float* __restrict__ b_ih,   // [256]
           const float* __restrict__ b_hh,   // [256]
           const float* __restrict__ fc_W,   // [30, 64]
           const float* __restrict__ fc_b,   // [30]
           float* __restrict__ out)          // [B, 30]
{
    __shared__ __align__(16) float g_sm[NB][NG];      // gates scratch
    __shared__ __align__(16) float h_sm[NB][HID];     // hidden state
    __shared__ __align__(16) float x_sm[NB][XCHUNK];  // x prefetch
    __shared__ __align__(16) float fcW_sm[NFC][HID];
    __shared__ float fcb_sm[NFC];

    const int tid = threadIdx.x;
    const int row = tid;                 // gate row 0..255 owned by this thread
    const int b0  = blockIdx.x * NB;     // first batch index of this block

    // --- W_hh row -> registers, packed as f32x2 pairs ---
    unsigned long long w2[HID / 2];
#pragma unroll
    for (int k = 0; k < HID / 2; ++k) {
        float a = W_hh[row * HID + 2 * k];
        float b = W_hh[row * HID + 2 * k + 1];
        w2[k] = pack2(a, b);
    }
    const float wih  = W_ih[row];
    const float bias = b_ih[row] + b_hh[row];

    // --- FC weights to smem; h init to zero ---
    for (int i = tid; i < NFC * HID; i += NTHREADS)
        (&fcW_sm[0][0])[i] = fc_W[i];
    for (int i = tid; i < NFC; i += NTHREADS)
        fcb_sm[i] = fc_b[i];
    for (int i = tid; i < NB * HID; i += NTHREADS)
        (&h_sm[0][0])[i] = 0.0f;

    // cell state: task tau = tid + 256*s  ->  b = tau/64, j = tau%64 (fixed map)
    float c_reg[NTASK];
#pragma unroll
    for (int s = 0; s < NTASK; ++s) c_reg[s] = 0.0f;

    for (int t = 0; t < SEQ_T; ++t) {
        // prefetch x for the next XCHUNK steps (clamped batch for tail block)
        if ((t & (XCHUNK - 1)) == 0) {
            for (int i = tid; i < NB * XCHUNK; i += NTHREADS) {
                int b  = i / XCHUNK;
                int tt = i % XCHUNK;
                int gb = b0 + b;
                if (gb >= NBATCH) gb = NBATCH - 1;
                (&x_sm[0][0])[i] = x[gb * SEQ_T + t + tt];
            }
        }
        __syncthreads();  // h (prev update) + x chunk visible

        // ---- matvec: gates[row] for all NB batch elements ----
        const int tx = t & (XCHUNK - 1);
        unsigned long long acc[NB];
#pragma unroll
        for (int b = 0; b < NB; ++b)
            acc[b] = pack2(fmaf(x_sm[b][tx], wih, bias), 0.0f);

#pragma unroll
        for (int k = 0; k < HID / 4; ++k) {
#pragma unroll
            for (int b = 0; b < NB; ++b) {
                ulonglong2 hv = *(const ulonglong2*)&h_sm[b][4 * k];  // LDS.128 bcast
                ffma2(acc[b], w2[2 * k],     hv.x);
                ffma2(acc[b], w2[2 * k + 1], hv.y);
            }
        }
#pragma unroll
        for (int b = 0; b < NB; ++b) {
            float lo, hi; unpack2(acc[b], lo, hi);
            g_sm[b][row] = lo + hi;
        }
        __syncthreads();  // gates ready

        // ---- pointwise update: c, h ----
#pragma unroll
        for (int s = 0; s < NTASK; ++s) {
            int task = tid + s * NTHREADS;
            int b = task >> 6;
            int j = task & 63;
            float gi = g_sm[b][j];
            float gf = g_sm[b][HID + j];
            float gg = g_sm[b][2 * HID + j];
            float go = g_sm[b][3 * HID + j];
            float ci = fmaf(sigm(gf), c_reg[s], sigm(gi) * tanh_fast(gg));
            c_reg[s] = ci;
            h_sm[b][j] = sigm(go) * tanh_fast(ci);
        }
        // next iteration's top-of-loop barrier orders h_sm writes vs reads
    }

    __syncthreads();  // final h ready

    // ---- FC: out[b, f] = h[b,:] . fc_W[f,:] + fc_b[f] ----
    for (int task = tid; task < NB * NFC; task += NTHREADS) {
        int b = task / NFC;
        int f = task % NFC;
        int gb = b0 + b;
        if (gb < NBATCH) {
            float s = fcb_sm[f];
#pragma unroll
            for (int k = 0; k < HID; ++k)
                s = fmaf(h_sm[b][k], fcW_sm[f][k], s);
            out[gb * NFC + f] = s;
        }
    }
}

extern "C" void kernel_launch(void* const* d_in, const int* in_sizes, int n_in,
                              void* d_out, int out_size) {
    const float* x    = (const float*)d_in[0];
    const float* W_ih = (const float*)d_in[1];
    const float* W_hh = (const float*)d_in[2];
    const float* b_ih = (const float*)d_in[3];
    const float* b_hh = (const float*)d_in[4];
    const float* fc_W = (const float*)d_in[5];
    const float* fc_b = (const float*)d_in[6];
    (void)in_sizes; (void)n_in; (void)out_size;

    const int grid = (NBATCH + NB - 1) / NB;  // 147 blocks, ~1 per SM
    lstm_fused<<<grid, NTHREADS>>>(x, W_ih, W_hh, b_ih, b_hh, fc_W, fc_b,
                                   (float*)d_out);
}

// round 3
// speedup vs baseline: 1.4636x; 1.4636x over previous
#include <cuda_runtime.h>

// LSTM (H=64, in=1, T=1024, B=4096) + Linear(64->30), fp32.
// 147 blocks (1/SM), 256 threads. Thread decomposition:
//   khalf = tid&1      : which half of the k (hidden) dimension, 32 values
//   j     = (tid>>1)&63: hidden unit -> owns gate rows {j,64+j,128+j,192+j}
//   bhalf = tid>>7     : which 14 of the 28 batches this thread processes
// Weights: 4 rows x 32 k = 128 floats in registers (f32x2 pairs), stored in
// rotated k-chunk order so the two khalves hit disjoint smem bank quads.
// Partial gate dots combined via shfl.bfly (lane^1). Updates done in a
// separate divergence-free phase (each lane owns 7 batches' c/h).
// h and x are ping-pong buffered -> one __syncthreads per step.

#define HID      64
#define SEQ_T    1024
#define NBATCH   4096
#define NFC      30
#define NB       28
#define NTHREADS 256
#define XCHUNK   32
#define BPT      14       // batches touched per thread in matvec
#define BOWN     7        // batches owned per thread for c/h update

__device__ __forceinline__ float fast_ex2(float x) {
    float r; asm("ex2.approx.f32 %0, %1;" : "=f"(r) : "f"(x)); return r;
}
__device__ __forceinline__ float fast_rcp(float x) {
    float r; asm("rcp.approx.f32 %0, %1;" : "=f"(r) : "f"(x)); return r;
}
__device__ __forceinline__ float sigm(float x) {
    return fast_rcp(1.0f + fast_ex2(-1.4426950408889634f * x));
}
__device__ __forceinline__ float tanh_fast(float x) {
    return 1.0f - 2.0f * fast_rcp(1.0f + fast_ex2(2.8853900817779268f * x));
}

__device__ __forceinline__ unsigned long long pack2(float lo, float hi) {
    unsigned long long r;
    asm("mov.b64 %0, {%1, %2};" : "=l"(r) : "f"(lo), "f"(hi));
    return r;
}
__device__ __forceinline__ void unpack2(unsigned long long v, float& lo, float& hi) {
    asm("mov.b64 {%0, %1}, %2;" : "=f"(lo), "=f"(hi) : "l"(v));
}
__device__ __forceinline__ void ffma2(unsigned long long& d,
                                      unsigned long long a,
                                      unsigned long long b) {
    asm("fma.rn.f32x2 %0, %1, %2, %0;" : "+l"(d) : "l"(a), "l"(b));
}

__global__ void __launch_bounds__(NTHREADS, 1)
lstm_fused(const float* __restrict__ x,      // [B, T]
           const float* __restrict__ W_ih,   // [256]
           const float* __restrict__ W_hh,   // [256, 64]
           const float* __restrict__ b_ih,   // [256]
           const float* __restrict__ b_hh,   // [256]
           const float* __restrict__ fc_W,   // [30, 64]
           const float* __restrict__ fc_b,   // [30]
           float* __restrict__ out)          // [B, 30]
{
    __shared__ __align__(16) float h_sm[2][NB][HID];     // ping-pong hidden
    __shared__ __align__(16) float x_sm[2][NB][XCHUNK];  // ping-pong x chunks
    __shared__ __align__(16) float fcW_sm[NFC][HID];
    __shared__ float fcb_sm[NFC];

    const int tid   = threadIdx.x;
    const int khalf = tid & 1;          // k half: 0 -> k[0..31], 1 -> k[32..63]
    const int j     = (tid >> 1) & 63;  // hidden unit
    const int bhalf = tid >> 7;         // batch half (0/1)
    const int b0    = blockIdx.x * NB;

    // --- weights: 4 gate rows, my 32 k-values, in rotated chunk order ---
    // chunk i covers global k = khalf*32 + ((i+khalf)&7)*4 .. +3
    const int rI = j, rF = HID + j, rG = 2 * HID + j, rO = 3 * HID + j;
    unsigned long long wI[16], wF[16], wG[16], wO[16];
    int hoff[8];  // byte offsets into an h row for chunk i
#pragma unroll
    for (int i = 0; i < 8; ++i) {
        int kb = khalf * 32 + (((i + khalf) & 7) << 2);  // k base of chunk i
        hoff[i] = kb * 4;
        wI[2*i]   = pack2(W_hh[rI*HID + kb],     W_hh[rI*HID + kb + 1]);
        wI[2*i+1] = pack2(W_hh[rI*HID + kb + 2], W_hh[rI*HID + kb + 3]);
        wF[2*i]   = pack2(W_hh[rF*HID + kb],     W_hh[rF*HID + kb + 1]);
        wF[2*i+1] = pack2(W_hh[rF*HID + kb + 2], W_hh[rF*HID + kb + 3]);
        wG[2*i]   = pack2(W_hh[rG*HID + kb],     W_hh[rG*HID + kb + 1]);
        wG[2*i+1] = pack2(W_hh[rG*HID + kb + 2], W_hh[rG*HID + kb + 3]);
        wO[2*i]   = pack2(W_hh[rO*HID + kb],     W_hh[rO*HID + kb + 1]);
        wO[2*i+1] = pack2(W_hh[rO*HID + kb + 2], W_hh[rO*HID + kb + 3]);
    }
    const float wihI = W_ih[rI], wihF = W_ih[rF], wihG = W_ih[rG], wihO = W_ih[rO];
    const float bI = b_ih[rI] + b_hh[rI];
    const float bF = b_ih[rF] + b_hh[rF];
    const float bG = b_ih[rG] + b_hh[rG];
    const float bO = b_ih[rO] + b_hh[rO];

    // --- FC weights to smem; h buf0 zero; x buf0 prologue fill (t=0..31) ---
    for (int i = tid; i < NFC * HID; i += NTHREADS)
        (&fcW_sm[0][0])[i] = fc_W[i];
    for (int i = tid; i < NFC; i += NTHREADS)
        fcb_sm[i] = fc_b[i];
    for (int i = tid; i < NB * HID; i += NTHREADS)
        (&h_sm[0][0][0])[i] = 0.0f;
    for (int i = tid; i < NB * XCHUNK; i += NTHREADS) {
        int b  = i / XCHUNK;
        int tt = i % XCHUNK;
        int gb = b0 + b; if (gb >= NBATCH) gb = NBATCH - 1;
        (&x_sm[0][0][0])[i] = x[gb * SEQ_T + tt];
    }

    float c_reg[BOWN];
#pragma unroll
    for (int s = 0; s < BOWN; ++s) c_reg[s] = 0.0f;

    for (int t = 0; t < SEQ_T; ++t) {
        const int rb = t & 1;           // h read buffer
        const int wb = rb ^ 1;          // h write buffer
        const int xb = (t >> 5) & 1;    // x read buffer

        // prefetch NEXT x chunk (steps t+32..t+63) into the other buffer
        if ((t & (XCHUNK - 1)) == 0 && t + XCHUNK < SEQ_T) {
            for (int i = tid; i < NB * XCHUNK; i += NTHREADS) {
                int b  = i / XCHUNK;
                int tt = i % XCHUNK;
                int gb = b0 + b; if (gb >= NBATCH) gb = NBATCH - 1;
                (&x_sm[xb ^ 1][0][0])[i] = x[gb * SEQ_T + t + XCHUNK + tt];
            }
        }
        __syncthreads();  // h[rb] writes from prev step + x visible

        const int tx = t & (XCHUNK - 1);
        float gq[BOWN][4];  // full gates for the 7 batches this thread owns

#pragma unroll
        for (int s = 0; s < BPT; ++s) {
            const int b = bhalf * BPT + s;
            const char* hbase = (const char*)&h_sm[rb][b][0];

            unsigned long long aI = 0ull, aF = 0ull, aG = 0ull, aO = 0ull;
#pragma unroll
            for (int i = 0; i < 8; ++i) {
                ulonglong2 hv = *(const ulonglong2*)(hbase + hoff[i]);
                ffma2(aI, wI[2*i], hv.x); ffma2(aI, wI[2*i+1], hv.y);
                ffma2(aF, wF[2*i], hv.x); ffma2(aF, wF[2*i+1], hv.y);
                ffma2(aG, wG[2*i], hv.x); ffma2(aG, wG[2*i+1], hv.y);
                ffma2(aO, wO[2*i], hv.x); ffma2(aO, wO[2*i+1], hv.y);
            }
            float lo, hi, pI, pF, pG, pO;
            unpack2(aI, lo, hi); pI = lo + hi;
            unpack2(aF, lo, hi); pF = lo + hi;
            unpack2(aG, lo, hi); pG = lo + hi;
            unpack2(aO, lo, hi); pO = lo + hi;

            // combine k-halves with the paired lane (lane ^ 1, same warp)
            unsigned long long p01 = pack2(pI, pF);
            unsigned long long p23 = pack2(pG, pO);
            unsigned long long o01 = __shfl_xor_sync(0xffffffffu, p01, 1);
            unsigned long long o23 = __shfl_xor_sync(0xffffffffu, p23, 1);
            float oI, oF, oG, oO;
            unpack2(o01, oI, oF);
            unpack2(o23, oG, oO);

            const float xv = x_sm[xb][b][tx];
            float gI = pI + oI + fmaf(xv, wihI, bI);
            float gF = pF + oF + fmaf(xv, wihF, bF);
            float gG = pG + oG + fmaf(xv, wihG, bG);
            float gO = pO + oO + fmaf(xv, wihO, bO);

            // keep only batches this lane owns: khalf0 -> s 0..6, khalf1 -> 7..13
            if (s < BOWN) {
                if (khalf == 0) { gq[s][0]=gI; gq[s][1]=gF; gq[s][2]=gG; gq[s][3]=gO; }
            } else {
                if (khalf == 1) { gq[s-BOWN][0]=gI; gq[s-BOWN][1]=gF; gq[s-BOWN][2]=gG; gq[s-BOWN][3]=gO; }
            }
        }

        // ---- divergence-free update: each lane updates its 7 owned batches ----
#pragma unroll
        for (int q = 0; q < BOWN; ++q) {
            const int b = bhalf * BPT + khalf * BOWN + q;
            float ci = fmaf(sigm(gq[q][1]), c_reg[q],
                            sigm(gq[q][0]) * tanh_fast(gq[q][2]));
            c_reg[q] = ci;
            h_sm[wb][b][j] = sigm(gq[q][3]) * tanh_fast(ci);
        }
    }

    __syncthreads();  // final h (in buffer 0, since SEQ_T is even) ready

    // ---- FC: out[b, f] = h[b,:] . fc_W[f,:] + fc_b[f] ----
    for (int task = tid; task < NB * NFC; task += NTHREADS) {
        int b = task / NFC;
        int f = task % NFC;
        int gb = b0 + b;
        if (gb < NBATCH) {
            float s = fcb_sm[f];
#pragma unroll
            for (int k = 0; k < HID; ++k)
                s = fmaf(h_sm[0][b][k], fcW_sm[f][k], s);
            out[gb * NFC + f] = s;
        }
    }
}

extern "C" void kernel_launch(void* const* d_in, const int* in_sizes, int n_in,
                              void* d_out, int out_size) {
    const float* x    = (const float*)d_in[0];
    const float* W_ih = (const float*)d_in[1];
    const float* W_hh = (const float*)d_in[2];
    const float* b_ih = (const float*)d_in[3];
    const float* b_hh = (const float*)d_in[4];
    const float* fc_W = (const float*)d_in[5];
    const float* fc_b = (const float*)d_in[6];
    (void)in_sizes; (void)n_in; (void)out_size;

    const int grid = (NBATCH + NB - 1) / NB;  // 147 blocks, 1 per SM
    lstm_fused<<<grid, NTHREADS>>>(x, W_ih, W_hh, b_ih, b_hh, fc_W, fc_b,
                                   (float*)d_out);
}